// round 10
// baseline (speedup 1.0000x reference)
#include <cuda_runtime.h>
#include <cuda_fp16.h>
#include <mma.h>
#include <cstdint>

using namespace nvcuda;

// Problem constants (fixed by dataset)
#define Nn 50000
#define Dd 128
#define Rr 3
#define Ee 800000
#define OUTD 64
#define ALPHAc 0.5f
#define BETA1c 0.6931471805599453f   // ln 2
#define BETA2c 0.4054651081081644f   // ln 1.5
#define SLOPEc 0.01f

// ---------------- scratch (device globals; no allocations allowed) ----------
__device__ __align__(256) __half g_xs  [(size_t)Rr * Nn * Dd];        // prescaled x (dinv_out)
__device__ __align__(256) __half g_h1h [((size_t)Nn + 64) * Dd];      // h1 fp16 (single copy), padded
__device__ __align__(256) __half g_aggh[((size_t)Rr * Nn + 64) * Dd]; // layer-1 operand, padded
__device__ __align__(256) __half g_xh  [((size_t)Nn + 64) * Dd];      // plain fp16 x, padded
__device__ __align__(256) __half g_z   [(size_t)Rr * Nn * OUTD];      // z_r = h1s_r @ G_r (fp16)
__device__ __align__(256) float  g_zx  [(size_t)Nn * OUTD];           // x @ Gx (fp32)
__device__ __align__(256) __half g_W1h [Rr * Dd * Dd];                // b1*W1 + (1-b1)*I
__device__ __align__(256) __half g_Gh  [Rr * Dd * OUTD];
__device__ __align__(256) __half g_Gxh [Dd * OUTD];
__device__ int   g_deg_out[Rr * Nn];
__device__ int   g_deg_in[Rr * Nn];
__device__ float g_dinv_out[Rr * Nn];
__device__ float g_dinv_in[Rr * Nn];
__device__ int   g_rowstart[Rr * Nn];
__device__ int   g_fillcur[Rr * Nn];
__device__ int   g_col[(size_t)Rr * Ee];
__device__ int   g_cursor[Rr];
__device__ float g_G[Rr * Dd * OUTD];
__device__ float g_c[OUTD];

// ---------------- init small state -------------------------------------------
__global__ void k_init() {
    int i = blockIdx.x * blockDim.x + threadIdx.x;
    if (i < Rr * Nn) { g_deg_out[i] = 0; g_deg_in[i] = 0; }
    if (i < Rr) g_cursor[i] = 0;
}

// ---------------- launch A: degree histogram + prep1 + prepw1 -----------------
#define DEG_BLOCKS  ((Rr * Ee + 255) / 256)                  // 9375
#define P1_BLOCKS   ((Rr * Dd * OUTD + 255) / 256)           // 96
#define PW1_BLOCKS  ((Rr * Dd * Dd + 255) / 256)             // 192
__global__ void k_degree_prep(const int* __restrict__ src, const int* __restrict__ dst,
                              const float* __restrict__ W2, const float* __restrict__ Wlin,
                              const float* __restrict__ W1) {
    int b = blockIdx.x;
    int t = threadIdx.x;
    if (b < DEG_BLOCKS) {
        int i = b * 256 + t;
        if (i >= Rr * Ee) return;
        int r = i / Ee;
        atomicAdd(&g_deg_out[r * Nn + src[i]], 1);
        atomicAdd(&g_deg_in [r * Nn + dst[i]], 1);
    } else if (b < DEG_BLOCKS + P1_BLOCKS) {
        int idx = (b - DEG_BLOCKS) * 256 + t;
        if (idx >= Rr * Dd * OUTD) return;
        int r = idx / (Dd * OUTD);
        int rem = idx % (Dd * OUTD);
        int i = rem / OUTD, j = rem % OUTD;
        const float* wrow = W2 + ((size_t)r * Dd + i) * Dd;
        float s = 0.f;
#pragma unroll 8
        for (int k = 0; k < Dd; ++k) s += wrow[k] * Wlin[k * OUTD + j];
        g_G[idx] = BETA2c * s + (1.f - BETA2c) * Wlin[rem];
    } else {
        int idx = (b - DEG_BLOCKS - P1_BLOCKS) * 256 + t;
        if (idx >= Rr * Dd * Dd) return;
        int ij = idx % (Dd * Dd);
        int i = ij >> 7, j = ij & 127;
        float v = BETA1c * W1[idx] + ((i == j) ? (1.f - BETA1c) : 0.f);
        g_W1h[idx] = __float2half(v);
    }
}

// ---------------- launch B: row starts + dinv + prep2 --------------------------
#define RS_XBLOCKS ((Nn + 255) / 256)                        // 196
#define RS_BLOCKS  (RS_XBLOCKS * Rr)                         // 588
#define P2_BLOCKS  ((Dd * OUTD + 255) / 256)                 // 32
__global__ void k_rowstart_prep(const float* __restrict__ b2, const float* __restrict__ Wlin,
                                const float* __restrict__ blin) {
    int b = blockIdx.x;
    int t = threadIdx.x;
    if (b < RS_BLOCKS) {
        int r = b / RS_XBLOCKS;
        int n = (b % RS_XBLOCKS) * 256 + t;
        int lane = t & 31;
        int d = (n < Nn) ? g_deg_in[r * Nn + n] : 0;
        int incl = d;
#pragma unroll
        for (int o = 1; o < 32; o <<= 1) {
            int v = __shfl_up_sync(0xffffffffu, incl, o);
            if (lane >= o) incl += v;
        }
        int total = __shfl_sync(0xffffffffu, incl, 31);
        int base = 0;
        if (lane == 31) base = atomicAdd(&g_cursor[r], total);
        base = __shfl_sync(0xffffffffu, base, 31);
        if (n < Nn) {
            int start = r * Ee + base + incl - d;
            g_rowstart[r * Nn + n] = start;
            g_fillcur [r * Nn + n] = start;
            int di = d < 1 ? 1 : d;
            g_dinv_in[r * Nn + n] = rsqrtf((float)di);
            int doo = g_deg_out[r * Nn + n]; if (doo < 1) doo = 1;
            g_dinv_out[r * Nn + n] = rsqrtf((float)doo);
        }
    } else {
        int idx = (b - RS_BLOCKS) * 256 + t;
        if (idx < Dd * OUTD) {
            float v0 = g_G[idx], v1 = g_G[Dd * OUTD + idx], v2 = g_G[2 * Dd * OUTD + idx];
            g_Gxh[idx] = __float2half((ALPHAc / 3.f) * (v0 + v1 + v2));
            const float sc = (1.f - ALPHAc) / 3.f;
            g_Gh[idx]                 = __float2half(v0 * sc);
            g_Gh[Dd * OUTD + idx]     = __float2half(v1 * sc);
            g_Gh[2 * Dd * OUTD + idx] = __float2half(v2 * sc);
        }
        if (idx < OUTD) {
            float cc = blin[idx];
            for (int k = 0; k < Dd; ++k)
                cc += (b2[k] + b2[Dd + k] + b2[2 * Dd + k]) * (1.f / 3.f) * Wlin[k * OUTD + idx];
            g_c[idx] = cc;
        }
    }
}

// ---------------- launch C: CSR fill + prescale --------------------------------
#define CF_BLOCKS  ((Rr * Ee + 255) / 256)                   // 9375
#define PS_BLOCKS  ((Nn * (Dd / 4) + 255) / 256)             // 6250
__global__ void k_csrfill_prescale(const int* __restrict__ src, const int* __restrict__ dst,
                                   const float* __restrict__ x) {
    int b = blockIdx.x;
    int t = threadIdx.x;
    if (b < CF_BLOCKS) {
        int i = b * 256 + t;
        if (i >= Rr * Ee) return;
        int r = i / Ee;
        int pos = atomicAdd(&g_fillcur[r * Nn + dst[i]], 1);
        g_col[pos] = src[i];
    } else {
        int i = (b - CF_BLOCKS) * 256 + t;
        if (i >= Nn * (Dd / 4)) return;
        int c4 = i & 31;
        int n = i >> 5;
        float4 v = __ldg(reinterpret_cast<const float4*>(x + (size_t)n * Dd) + c4);
        __half2 q0 = __floats2half2_rn(v.x, v.y);
        __half2 q1 = __floats2half2_rn(v.z, v.w);
        uint2 w;
        w.x = *reinterpret_cast<unsigned*>(&q0);
        w.y = *reinterpret_cast<unsigned*>(&q1);
        *reinterpret_cast<uint2*>(g_xh + (size_t)n * Dd + c4 * 4) = w;
#pragma unroll
        for (int r = 0; r < Rr; ++r) {
            float s = __ldg(g_dinv_out + r * Nn + n);
            __half2 p0 = __floats2half2_rn(v.x * s, v.y * s);
            __half2 p1 = __floats2half2_rn(v.z * s, v.w * s);
            uint2 u;
            u.x = *reinterpret_cast<unsigned*>(&p0);
            u.y = *reinterpret_cast<unsigned*>(&p1);
            *reinterpret_cast<uint2*>(g_xs + ((size_t)r * Nn + n) * Dd + c4 * 4) = u;
        }
    }
}

// ---------------- fp16 helpers --------------------------------------------------
__device__ __forceinline__ void acc_h4(float4& acc, uint2 u) {
    __half2 a = *reinterpret_cast<__half2*>(&u.x);
    __half2 b = *reinterpret_cast<__half2*>(&u.y);
    float2 fa = __half22float2(a), fb = __half22float2(b);
    acc.x += fa.x; acc.y += fa.y; acc.z += fb.x; acc.w += fb.y;
}

// ---------------- gather (layer 1): aggh = (1-a)*dinv_in*sum + a*x -------------
__launch_bounds__(256)
__global__ void k_gather1() {
    int gw = (blockIdx.x * blockDim.x + threadIdx.x) >> 5;   // (r,n) index
    if (gw >= Rr * Nn) return;
    int lane = threadIdx.x & 31;
    int n = gw % Nn;
    const __half* base = g_xs + (size_t)(gw / Nn) * Nn * Dd;

    int beg = __ldg(g_rowstart + gw);
    int end = beg + __ldg(g_deg_in + gw);
    float4 acc = make_float4(0.f, 0.f, 0.f, 0.f);
    int e = beg;
#pragma unroll 1
    for (; e + 4 <= end; e += 4) {
        int s0 = __ldg(g_col + e);
        int s1 = __ldg(g_col + e + 1);
        int s2 = __ldg(g_col + e + 2);
        int s3 = __ldg(g_col + e + 3);
        uint2 u0 = __ldg(reinterpret_cast<const uint2*>(base + (size_t)s0 * Dd) + lane);
        uint2 u1 = __ldg(reinterpret_cast<const uint2*>(base + (size_t)s1 * Dd) + lane);
        uint2 u2 = __ldg(reinterpret_cast<const uint2*>(base + (size_t)s2 * Dd) + lane);
        uint2 u3 = __ldg(reinterpret_cast<const uint2*>(base + (size_t)s3 * Dd) + lane);
        acc_h4(acc, u0); acc_h4(acc, u1); acc_h4(acc, u2); acc_h4(acc, u3);
    }
#pragma unroll 1
    for (; e < end; ++e) {
        int s0 = __ldg(g_col + e);
        uint2 u0 = __ldg(reinterpret_cast<const uint2*>(base + (size_t)s0 * Dd) + lane);
        acc_h4(acc, u0);
    }
    float sc = __ldg(g_dinv_in + gw) * (1.f - ALPHAc);
    uint2 xv = __ldg(reinterpret_cast<const uint2*>(g_xh + (size_t)n * Dd) + lane);
    float4 xf = make_float4(0.f, 0.f, 0.f, 0.f);
    acc_h4(xf, xv);
    float4 o;
    o.x = acc.x * sc + ALPHAc * xf.x;
    o.y = acc.y * sc + ALPHAc * xf.y;
    o.z = acc.z * sc + ALPHAc * xf.z;
    o.w = acc.w * sc + ALPHAc * xf.w;
    __half2 p0 = __floats2half2_rn(o.x, o.y);
    __half2 p1 = __floats2half2_rn(o.z, o.w);
    uint2 u;
    u.x = *reinterpret_cast<unsigned*>(&p0);
    u.y = *reinterpret_cast<unsigned*>(&p1);
    *reinterpret_cast<uint2*>(g_aggh + (size_t)gw * Dd + lane * 4) = u;
}

// pack 8 floats -> 8 halfs (16B)
__device__ __forceinline__ uint4 pack_half8(const float* v) {
    __half2 p0 = __floats2half2_rn(v[0], v[1]);
    __half2 p1 = __floats2half2_rn(v[2], v[3]);
    __half2 p2 = __floats2half2_rn(v[4], v[5]);
    __half2 p3 = __floats2half2_rn(v[6], v[7]);
    uint4 u;
    u.x = *reinterpret_cast<unsigned*>(&p0);
    u.y = *reinterpret_cast<unsigned*>(&p1);
    u.z = *reinterpret_cast<unsigned*>(&p2);
    u.w = *reinterpret_cast<unsigned*>(&p3);
    return u;
}

// copy a 64x128 fp16 tile global -> smem (stride 136), coalesced uint4
__device__ __forceinline__ void stage_tile(__half* Ah, const __half* __restrict__ Ab,
                                           int tid) {
#pragma unroll
    for (int it = 0; it < 4; ++it) {
        int idx = it * 256 + tid;            // 1024 uint4 total
        int row = idx >> 4, c8 = idx & 15;
        uint4 u = __ldg(reinterpret_cast<const uint4*>(Ab + (size_t)row * Dd) + c8);
        *reinterpret_cast<uint4*>(Ah + row * 136 + c8 * 8) = u;
    }
}

// ---------------- layer-1 GEMM: smem-staged A, tensor cores -------------------
// C = aggh_r @ W1'_r ; epi: +bias, leaky, 1/3 mean; writes h1 fp16 (single copy)
__launch_bounds__(256)
__global__ void k_gemm1(const float* __restrict__ b1) {
    __shared__ __align__(16) __half Ah[64 * 136];   // 17408 B
    __shared__ __align__(16) float  Cs[64 * 132];   // 33792 B
    int tid = threadIdx.x;
    int warp = tid >> 5;
    int ty = tid >> 4, tx = tid & 15;
    int wr = warp >> 1, wc = warp & 1;
    int n0 = blockIdx.x << 6;

    float hacc[4][8];
#pragma unroll
    for (int i = 0; i < 4; ++i)
#pragma unroll
        for (int j = 0; j < 8; ++j) hacc[i][j] = 0.f;

    for (int r = 0; r < Rr; ++r) {
        if (r > 0) __syncthreads();
        stage_tile(Ah, g_aggh + ((size_t)r * Nn + n0) * Dd, tid);
        __syncthreads();

        wmma::fragment<wmma::accumulator, 16, 16, 16, float> acc[4];
#pragma unroll
        for (int f = 0; f < 4; ++f) wmma::fill_fragment(acc[f], 0.f);
        const __half* Bg = g_W1h + (size_t)r * Dd * Dd;
#pragma unroll
        for (int k = 0; k < 8; ++k) {
            wmma::fragment<wmma::matrix_a, 16, 16, 16, __half, wmma::row_major> af;
            wmma::load_matrix_sync(af, Ah + (wr * 16) * 136 + k * 16, 136);
#pragma unroll
            for (int f = 0; f < 4; ++f) {
                wmma::fragment<wmma::matrix_b, 16, 16, 16, __half, wmma::row_major> bf;
                wmma::load_matrix_sync(bf, Bg + (k * 16) * Dd + wc * 64 + f * 16, Dd);
                wmma::mma_sync(acc[f], af, bf, acc[f]);
            }
        }
#pragma unroll
        for (int f = 0; f < 4; ++f)
            wmma::store_matrix_sync(Cs + (wr * 16) * 132 + wc * 64 + f * 16, acc[f], 132,
                                    wmma::mem_row_major);
        __syncthreads();

#pragma unroll
        for (int i = 0; i < 4; ++i) {
            int row = ty * 4 + i;
#pragma unroll
            for (int j = 0; j < 8; ++j) {
                int col = tx * 8 + j;
                float v = Cs[row * 132 + col] + b1[r * Dd + col];
                v = v >= 0.f ? v : SLOPEc * v;
                hacc[i][j] += v * (1.f / 3.f);
            }
        }
    }

    // write h1 fp16 (single copy)
#pragma unroll
    for (int i = 0; i < 4; ++i) {
        int n = n0 + ty * 4 + i;
        if (n < Nn) {
            uint4 u = pack_half8(hacc[i]);
            *reinterpret_cast<uint4*>(g_h1h + (size_t)n * Dd + tx * 8) = u;
        }
    }
}

// ---------------- z GEMM: z_r = (h1 * dinv_out_r) @ G_r ; zx = x @ Gx ----------
// grid.y in [0,3]: y<3 -> z_r fp16; y==3 -> zx fp32
__launch_bounds__(256)
__global__ void k_gemmz() {
    __shared__ __align__(16) __half Ah[64 * 136];
    __shared__ __align__(16) float  Cs[64 * 68];
    int tid = threadIdx.x;
    int warp = tid >> 5;
    int wr = warp >> 1, wc = warp & 1;
    int n0 = blockIdx.x << 6;
    int y = blockIdx.y;

    // stage A: 64x128 fp16 with per-row scale (y<3) from h1h, or plain xh (y==3)
    const __half* Asrc = (y < 3) ? g_h1h : g_xh;
#pragma unroll
    for (int it = 0; it < 8; ++it) {
        int idx = it * 256 + tid;            // 2048 uint2 total
        int row = idx >> 5, c4 = idx & 31;
        uint2 u = __ldg(reinterpret_cast<const uint2*>(Asrc + (size_t)(n0 + row) * Dd) + c4);
        if (y < 3) {
            int n = n0 + row;
            float s = (n < Nn) ? __ldg(g_dinv_out + y * Nn + n) : 0.f;
            float4 f = make_float4(0.f, 0.f, 0.f, 0.f);
            acc_h4(f, u);
            __half2 p0 = __floats2half2_rn(f.x * s, f.y * s);
            __half2 p1 = __floats2half2_rn(f.z * s, f.w * s);
            u.x = *reinterpret_cast<unsigned*>(&p0);
            u.y = *reinterpret_cast<unsigned*>(&p1);
        }
        *reinterpret_cast<uint2*>(Ah + row * 136 + c4 * 4) = u;
    }
    __syncthreads();

    const __half* Bb = (y < 3) ? (g_Gh + (size_t)y * Dd * OUTD) : g_Gxh;
    wmma::fragment<wmma::accumulator, 16, 16, 16, float> acc[2];
#pragma unroll
    for (int f = 0; f < 2; ++f) wmma::fill_fragment(acc[f], 0.f);
#pragma unroll
    for (int k = 0; k < 8; ++k) {
        wmma::fragment<wmma::matrix_a, 16, 16, 16, __half, wmma::row_major> af;
        wmma::load_matrix_sync(af, Ah + (wr * 16) * 136 + k * 16, 136);
#pragma unroll
        for (int f = 0; f < 2; ++f) {
            wmma::fragment<wmma::matrix_b, 16, 16, 16, __half, wmma::row_major> bf;
            wmma::load_matrix_sync(bf, Bb + (k * 16) * OUTD + wc * 32 + f * 16, OUTD);
            wmma::mma_sync(acc[f], af, bf, acc[f]);
        }
    }
#pragma unroll
    for (int f = 0; f < 2; ++f)
        wmma::store_matrix_sync(Cs + (wr * 16) * 68 + wc * 32 + f * 16, acc[f], 68,
                                wmma::mem_row_major);
    __syncthreads();

    if (y < 3) {
        // pack to fp16 z: 64 rows x 32 uint (2 halfs each)
#pragma unroll
        for (int it = 0; it < 8; ++it) {
            int idx = it * 256 + tid;        // 2048
            int row = idx >> 5, cp = idx & 31;
            int n = n0 + row;
            if (n < Nn) {
                __half2 p = __floats2half2_rn(Cs[row * 68 + cp * 2], Cs[row * 68 + cp * 2 + 1]);
                *(reinterpret_cast<unsigned*>(g_z + ((size_t)y * Nn + n) * OUTD) + cp) =
                    *reinterpret_cast<unsigned*>(&p);
            }
        }
    } else {
        // store fp32 zx
#pragma unroll
        for (int it = 0; it < 8; ++it) {
            int idx = it * 256 + tid;
            int row = idx >> 5, cp = idx & 31;
            int n = n0 + row;
            if (n < Nn) {
                float2 p = make_float2(Cs[row * 68 + cp * 2], Cs[row * 68 + cp * 2 + 1]);
                *(reinterpret_cast<float2*>(g_zx + (size_t)n * OUTD) + cp) = p;
            }
        }
    }
}

// ---------------- combine: out[n] = sum_r dinv_in*gather(z_r) + zx + c ---------
// one warp per node; lane handles output cols {2*lane, 2*lane+1}
__launch_bounds__(256)
__global__ void k_combine(float* __restrict__ out) {
    int n = (blockIdx.x * blockDim.x + threadIdx.x) >> 5;
    if (n >= Nn) return;
    int lane = threadIdx.x & 31;

    float2 tot = make_float2(0.f, 0.f);
#pragma unroll
    for (int r = 0; r < Rr; ++r) {
        int gw = r * Nn + n;
        int beg = __ldg(g_rowstart + gw);
        int end = beg + __ldg(g_deg_in + gw);
        float2 acc = make_float2(0.f, 0.f);
        int e = beg;
        const __half* zb = g_z + (size_t)r * Nn * OUTD;
#pragma unroll 1
        for (; e + 4 <= end; e += 4) {
            int s0 = __ldg(g_col + e);
            int s1 = __ldg(g_col + e + 1);
            int s2 = __ldg(g_col + e + 2);
            int s3 = __ldg(g_col + e + 3);
            unsigned u0 = __ldg(reinterpret_cast<const unsigned*>(zb + (size_t)s0 * OUTD) + lane);
            unsigned u1 = __ldg(reinterpret_cast<const unsigned*>(zb + (size_t)s1 * OUTD) + lane);
            unsigned u2 = __ldg(reinterpret_cast<const unsigned*>(zb + (size_t)s2 * OUTD) + lane);
            unsigned u3 = __ldg(reinterpret_cast<const unsigned*>(zb + (size_t)s3 * OUTD) + lane);
            float2 f0 = __half22float2(*reinterpret_cast<__half2*>(&u0));
            float2 f1 = __half22float2(*reinterpret_cast<__half2*>(&u1));
            float2 f2 = __half22float2(*reinterpret_cast<__half2*>(&u2));
            float2 f3 = __half22float2(*reinterpret_cast<__half2*>(&u3));
            acc.x += f0.x + f1.x + f2.x + f3.x;
            acc.y += f0.y + f1.y + f2.y + f3.y;
        }
#pragma unroll 1
        for (; e < end; ++e) {
            int s0 = __ldg(g_col + e);
            unsigned u0 = __ldg(reinterpret_cast<const unsigned*>(zb + (size_t)s0 * OUTD) + lane);
            float2 f0 = __half22float2(*reinterpret_cast<__half2*>(&u0));
            acc.x += f0.x; acc.y += f0.y;
        }
        float di = __ldg(g_dinv_in + gw);
        tot.x += acc.x * di;
        tot.y += acc.y * di;
    }
    float2 zx = __ldg(reinterpret_cast<const float2*>(g_zx + (size_t)n * OUTD) + lane);
    float2 o;
    o.x = tot.x + zx.x + g_c[lane * 2];
    o.y = tot.y + zx.y + g_c[lane * 2 + 1];
    *(reinterpret_cast<float2*>(out + (size_t)n * OUTD) + lane) = o;
}

// ---------------- launch ------------------------------------------------------
extern "C" void kernel_launch(void* const* d_in, const int* in_sizes, int n_in,
                              void* d_out, int out_size) {
    const float* x    = (const float*)d_in[0];
    const int*   src  = (const int*)  d_in[1];
    const int*   dst  = (const int*)  d_in[2];
    const float* W1   = (const float*)d_in[3];
    const float* b1   = (const float*)d_in[4];
    const float* W2   = (const float*)d_in[5];
    const float* b2   = (const float*)d_in[6];
    const float* Wlin = (const float*)d_in[7];
    const float* blin = (const float*)d_in[8];
    float* out = (float*)d_out;

    k_init<<<(Rr * Nn + 255) / 256, 256>>>();
    k_degree_prep<<<DEG_BLOCKS + P1_BLOCKS + PW1_BLOCKS, 256>>>(src, dst, W2, Wlin, W1);
    k_rowstart_prep<<<RS_BLOCKS + P2_BLOCKS, 256>>>(b2, Wlin, blin);
    k_csrfill_prescale<<<CF_BLOCKS + PS_BLOCKS, 256>>>(src, dst, x);

    const int gather_blocks = (Rr * Nn * 32 + 255) / 256;   // one warp per (r,n)
    // layer 1
    k_gather1<<<gather_blocks, 256>>>();
    k_gemm1<<<(Nn + 63) / 64, 256>>>(b1);
    // layer 2: project then gather 64-dim rows
    dim3 zgrid((Nn + 63) / 64, 4);
    k_gemmz<<<zgrid, 256>>>();
    k_combine<<<(Nn * 32 + 255) / 256, 256>>>(out);
}

// round 11
// speedup vs baseline: 1.4073x; 1.4073x over previous
#include <cuda_runtime.h>
#include <cuda_fp16.h>
#include <mma.h>
#include <cstdint>

using namespace nvcuda;

// Problem constants (fixed by dataset)
#define Nn 50000
#define Dd 128
#define Rr 3
#define Ee 800000
#define OUTD 64
#define ALPHAc 0.5f
#define BETA1c 0.6931471805599453f   // ln 2
#define BETA2c 0.4054651081081644f   // ln 1.5
#define SLOPEc 0.01f

// ---------------- scratch (device globals; no allocations allowed) ----------
__device__ __align__(256) __half g_xs  [(size_t)Rr * Nn * Dd];        // prescaled x (dinv_out)
__device__ __align__(256) __half g_h1h [((size_t)Nn + 64) * Dd];      // h1 fp16 (single copy), padded
__device__ __align__(256) __half g_aggh[((size_t)Rr * Nn + 64) * Dd]; // layer-1 operand, padded
__device__ __align__(256) __half g_xh  [((size_t)Nn + 64) * Dd];      // plain fp16 x, padded
__device__ __align__(256) __half g_z   [(size_t)Rr * Nn * OUTD];      // z_r = (h1*d_out_r) @ G_r
__device__ __align__(256) __half g_W1h [Rr * Dd * Dd];                // b1*W1 + (1-b1)*I
__device__ __align__(256) __half g_Gh  [Rr * Dd * OUTD];
__device__ __align__(256) __half g_Gxh [Dd * OUTD];
__device__ int   g_deg_out[Rr * Nn];
__device__ int   g_deg_in[Rr * Nn];
__device__ float g_dinv_out[Rr * Nn];
__device__ float g_dinv_in[Rr * Nn];
__device__ int   g_rowstart[Rr * Nn];
__device__ int   g_fillcur[Rr * Nn];
__device__ int   g_col[(size_t)Rr * Ee];
__device__ int   g_cursor[Rr];
__device__ float g_G[Rr * Dd * OUTD];
__device__ float g_c[OUTD];

// ---------------- init small state -------------------------------------------
__global__ void k_init() {
    int i = blockIdx.x * blockDim.x + threadIdx.x;
    if (i < Rr * Nn) { g_deg_out[i] = 0; g_deg_in[i] = 0; }
    if (i < Rr) g_cursor[i] = 0;
}

// ---------------- launch A: degree histogram + prep1 + prepw1 -----------------
#define DEG_BLOCKS  ((Rr * Ee + 255) / 256)                  // 9375
#define P1_BLOCKS   ((Rr * Dd * OUTD + 255) / 256)           // 96
#define PW1_BLOCKS  ((Rr * Dd * Dd + 255) / 256)             // 192
__global__ void k_degree_prep(const int* __restrict__ src, const int* __restrict__ dst,
                              const float* __restrict__ W2, const float* __restrict__ Wlin,
                              const float* __restrict__ W1) {
    int b = blockIdx.x;
    int t = threadIdx.x;
    if (b < DEG_BLOCKS) {
        int i = b * 256 + t;
        if (i >= Rr * Ee) return;
        int r = i / Ee;
        atomicAdd(&g_deg_out[r * Nn + src[i]], 1);
        atomicAdd(&g_deg_in [r * Nn + dst[i]], 1);
    } else if (b < DEG_BLOCKS + P1_BLOCKS) {
        int idx = (b - DEG_BLOCKS) * 256 + t;
        if (idx >= Rr * Dd * OUTD) return;
        int r = idx / (Dd * OUTD);
        int rem = idx % (Dd * OUTD);
        int i = rem / OUTD, j = rem % OUTD;
        const float* wrow = W2 + ((size_t)r * Dd + i) * Dd;
        float s = 0.f;
#pragma unroll 8
        for (int k = 0; k < Dd; ++k) s += wrow[k] * Wlin[k * OUTD + j];
        g_G[idx] = BETA2c * s + (1.f - BETA2c) * Wlin[rem];
    } else {
        int idx = (b - DEG_BLOCKS - P1_BLOCKS) * 256 + t;
        if (idx >= Rr * Dd * Dd) return;
        int ij = idx % (Dd * Dd);
        int i = ij >> 7, j = ij & 127;
        float v = BETA1c * W1[idx] + ((i == j) ? (1.f - BETA1c) : 0.f);
        g_W1h[idx] = __float2half(v);
    }
}

// ---------------- launch B: row starts + dinv + prep2 --------------------------
#define RS_XBLOCKS ((Nn + 255) / 256)                        // 196
#define RS_BLOCKS  (RS_XBLOCKS * Rr)                         // 588
#define P2_BLOCKS  ((Dd * OUTD + 255) / 256)                 // 32
__global__ void k_rowstart_prep(const float* __restrict__ b2, const float* __restrict__ Wlin,
                                const float* __restrict__ blin) {
    int b = blockIdx.x;
    int t = threadIdx.x;
    if (b < RS_BLOCKS) {
        int r = b / RS_XBLOCKS;
        int n = (b % RS_XBLOCKS) * 256 + t;
        int lane = t & 31;
        int d = (n < Nn) ? g_deg_in[r * Nn + n] : 0;
        int incl = d;
#pragma unroll
        for (int o = 1; o < 32; o <<= 1) {
            int v = __shfl_up_sync(0xffffffffu, incl, o);
            if (lane >= o) incl += v;
        }
        int total = __shfl_sync(0xffffffffu, incl, 31);
        int base = 0;
        if (lane == 31) base = atomicAdd(&g_cursor[r], total);
        base = __shfl_sync(0xffffffffu, base, 31);
        if (n < Nn) {
            int start = r * Ee + base + incl - d;
            g_rowstart[r * Nn + n] = start;
            g_fillcur [r * Nn + n] = start;
            int di = d < 1 ? 1 : d;
            g_dinv_in[r * Nn + n] = rsqrtf((float)di);
            int doo = g_deg_out[r * Nn + n]; if (doo < 1) doo = 1;
            g_dinv_out[r * Nn + n] = rsqrtf((float)doo);
        }
    } else {
        int idx = (b - RS_BLOCKS) * 256 + t;
        if (idx < Dd * OUTD) {
            float v0 = g_G[idx], v1 = g_G[Dd * OUTD + idx], v2 = g_G[2 * Dd * OUTD + idx];
            g_Gxh[idx] = __float2half((ALPHAc / 3.f) * (v0 + v1 + v2));
            const float sc = (1.f - ALPHAc) / 3.f;
            g_Gh[idx]                 = __float2half(v0 * sc);
            g_Gh[Dd * OUTD + idx]     = __float2half(v1 * sc);
            g_Gh[2 * Dd * OUTD + idx] = __float2half(v2 * sc);
        }
        if (idx < OUTD) {
            float cc = blin[idx];
            for (int k = 0; k < Dd; ++k)
                cc += (b2[k] + b2[Dd + k] + b2[2 * Dd + k]) * (1.f / 3.f) * Wlin[k * OUTD + idx];
            g_c[idx] = cc;
        }
    }
}

// ---------------- launch C: CSR fill + prescale --------------------------------
#define CF_BLOCKS  ((Rr * Ee + 255) / 256)                   // 9375
#define PS_BLOCKS  ((Nn * (Dd / 4) + 255) / 256)             // 6250
__global__ void k_csrfill_prescale(const int* __restrict__ src, const int* __restrict__ dst,
                                   const float* __restrict__ x) {
    int b = blockIdx.x;
    int t = threadIdx.x;
    if (b < CF_BLOCKS) {
        int i = b * 256 + t;
        if (i >= Rr * Ee) return;
        int r = i / Ee;
        int pos = atomicAdd(&g_fillcur[r * Nn + dst[i]], 1);
        g_col[pos] = src[i];
    } else {
        int i = (b - CF_BLOCKS) * 256 + t;
        if (i >= Nn * (Dd / 4)) return;
        int c4 = i & 31;
        int n = i >> 5;
        float4 v = __ldg(reinterpret_cast<const float4*>(x + (size_t)n * Dd) + c4);
        __half2 q0 = __floats2half2_rn(v.x, v.y);
        __half2 q1 = __floats2half2_rn(v.z, v.w);
        uint2 w;
        w.x = *reinterpret_cast<unsigned*>(&q0);
        w.y = *reinterpret_cast<unsigned*>(&q1);
        *reinterpret_cast<uint2*>(g_xh + (size_t)n * Dd + c4 * 4) = w;
#pragma unroll
        for (int r = 0; r < Rr; ++r) {
            float s = __ldg(g_dinv_out + r * Nn + n);
            __half2 p0 = __floats2half2_rn(v.x * s, v.y * s);
            __half2 p1 = __floats2half2_rn(v.z * s, v.w * s);
            uint2 u;
            u.x = *reinterpret_cast<unsigned*>(&p0);
            u.y = *reinterpret_cast<unsigned*>(&p1);
            *reinterpret_cast<uint2*>(g_xs + ((size_t)r * Nn + n) * Dd + c4 * 4) = u;
        }
    }
}

// ---------------- fp16 helpers --------------------------------------------------
__device__ __forceinline__ void acc_h4(float4& acc, uint2 u) {
    __half2 a = *reinterpret_cast<__half2*>(&u.x);
    __half2 b = *reinterpret_cast<__half2*>(&u.y);
    float2 fa = __half22float2(a), fb = __half22float2(b);
    acc.x += fa.x; acc.y += fa.y; acc.z += fb.x; acc.w += fb.y;
}

// ---------------- gather (layer 1): aggh = (1-a)*dinv_in*sum + a*x -------------
__launch_bounds__(256)
__global__ void k_gather1() {
    int gw = (blockIdx.x * blockDim.x + threadIdx.x) >> 5;   // (r,n) index
    if (gw >= Rr * Nn) return;
    int lane = threadIdx.x & 31;
    int n = gw % Nn;
    const __half* base = g_xs + (size_t)(gw / Nn) * Nn * Dd;

    int beg = __ldg(g_rowstart + gw);
    int end = beg + __ldg(g_deg_in + gw);
    float4 acc = make_float4(0.f, 0.f, 0.f, 0.f);
    int e = beg;
#pragma unroll 1
    for (; e + 4 <= end; e += 4) {
        int s0 = __ldg(g_col + e);
        int s1 = __ldg(g_col + e + 1);
        int s2 = __ldg(g_col + e + 2);
        int s3 = __ldg(g_col + e + 3);
        uint2 u0 = __ldg(reinterpret_cast<const uint2*>(base + (size_t)s0 * Dd) + lane);
        uint2 u1 = __ldg(reinterpret_cast<const uint2*>(base + (size_t)s1 * Dd) + lane);
        uint2 u2 = __ldg(reinterpret_cast<const uint2*>(base + (size_t)s2 * Dd) + lane);
        uint2 u3 = __ldg(reinterpret_cast<const uint2*>(base + (size_t)s3 * Dd) + lane);
        acc_h4(acc, u0); acc_h4(acc, u1); acc_h4(acc, u2); acc_h4(acc, u3);
    }
#pragma unroll 1
    for (; e < end; ++e) {
        int s0 = __ldg(g_col + e);
        uint2 u0 = __ldg(reinterpret_cast<const uint2*>(base + (size_t)s0 * Dd) + lane);
        acc_h4(acc, u0);
    }
    float sc = __ldg(g_dinv_in + gw) * (1.f - ALPHAc);
    uint2 xv = __ldg(reinterpret_cast<const uint2*>(g_xh + (size_t)n * Dd) + lane);
    float4 xf = make_float4(0.f, 0.f, 0.f, 0.f);
    acc_h4(xf, xv);
    float4 o;
    o.x = acc.x * sc + ALPHAc * xf.x;
    o.y = acc.y * sc + ALPHAc * xf.y;
    o.z = acc.z * sc + ALPHAc * xf.z;
    o.w = acc.w * sc + ALPHAc * xf.w;
    __half2 p0 = __floats2half2_rn(o.x, o.y);
    __half2 p1 = __floats2half2_rn(o.z, o.w);
    uint2 u;
    u.x = *reinterpret_cast<unsigned*>(&p0);
    u.y = *reinterpret_cast<unsigned*>(&p1);
    *reinterpret_cast<uint2*>(g_aggh + (size_t)gw * Dd + lane * 4) = u;
}

// pack 8 floats -> 8 halfs (16B)
__device__ __forceinline__ uint4 pack_half8(const float* v) {
    __half2 p0 = __floats2half2_rn(v[0], v[1]);
    __half2 p1 = __floats2half2_rn(v[2], v[3]);
    __half2 p2 = __floats2half2_rn(v[4], v[5]);
    __half2 p3 = __floats2half2_rn(v[6], v[7]);
    uint4 u;
    u.x = *reinterpret_cast<unsigned*>(&p0);
    u.y = *reinterpret_cast<unsigned*>(&p1);
    u.z = *reinterpret_cast<unsigned*>(&p2);
    u.w = *reinterpret_cast<unsigned*>(&p3);
    return u;
}

// copy a 64x128 fp16 tile global -> smem (stride 136), coalesced uint4
__device__ __forceinline__ void stage_tile(__half* Ah, const __half* __restrict__ Ab,
                                           int tid) {
#pragma unroll
    for (int it = 0; it < 4; ++it) {
        int idx = it * 256 + tid;            // 1024 uint4 total
        int row = idx >> 4, c8 = idx & 15;
        uint4 u = __ldg(reinterpret_cast<const uint4*>(Ab + (size_t)row * Dd) + c8);
        *reinterpret_cast<uint4*>(Ah + row * 136 + c8 * 8) = u;
    }
}

// ---------------- layer-1 GEMM: smem-staged A, tensor cores -------------------
// C = aggh_r @ W1'_r ; epi: +bias, leaky, 1/3 mean; writes h1 fp16 (single copy)
__launch_bounds__(256)
__global__ void k_gemm1(const float* __restrict__ b1) {
    __shared__ __align__(16) __half Ah[64 * 136];   // 17408 B
    __shared__ __align__(16) float  Cs[64 * 132];   // 33792 B
    int tid = threadIdx.x;
    int warp = tid >> 5;
    int ty = tid >> 4, tx = tid & 15;
    int wr = warp >> 1, wc = warp & 1;
    int n0 = blockIdx.x << 6;

    float hacc[4][8];
#pragma unroll
    for (int i = 0; i < 4; ++i)
#pragma unroll
        for (int j = 0; j < 8; ++j) hacc[i][j] = 0.f;

    for (int r = 0; r < Rr; ++r) {
        if (r > 0) __syncthreads();
        stage_tile(Ah, g_aggh + ((size_t)r * Nn + n0) * Dd, tid);
        __syncthreads();

        wmma::fragment<wmma::accumulator, 16, 16, 16, float> acc[4];
#pragma unroll
        for (int f = 0; f < 4; ++f) wmma::fill_fragment(acc[f], 0.f);
        const __half* Bg = g_W1h + (size_t)r * Dd * Dd;
#pragma unroll
        for (int k = 0; k < 8; ++k) {
            wmma::fragment<wmma::matrix_a, 16, 16, 16, __half, wmma::row_major> af;
            wmma::load_matrix_sync(af, Ah + (wr * 16) * 136 + k * 16, 136);
#pragma unroll
            for (int f = 0; f < 4; ++f) {
                wmma::fragment<wmma::matrix_b, 16, 16, 16, __half, wmma::row_major> bf;
                wmma::load_matrix_sync(bf, Bg + (k * 16) * Dd + wc * 64 + f * 16, Dd);
                wmma::mma_sync(acc[f], af, bf, acc[f]);
            }
        }
#pragma unroll
        for (int f = 0; f < 4; ++f)
            wmma::store_matrix_sync(Cs + (wr * 16) * 132 + wc * 64 + f * 16, acc[f], 132,
                                    wmma::mem_row_major);
        __syncthreads();

#pragma unroll
        for (int i = 0; i < 4; ++i) {
            int row = ty * 4 + i;
#pragma unroll
            for (int j = 0; j < 8; ++j) {
                int col = tx * 8 + j;
                float v = Cs[row * 132 + col] + b1[r * Dd + col];
                v = v >= 0.f ? v : SLOPEc * v;
                hacc[i][j] += v * (1.f / 3.f);
            }
        }
    }

    // write h1 fp16 (single copy)
#pragma unroll
    for (int i = 0; i < 4; ++i) {
        int n = n0 + ty * 4 + i;
        if (n < Nn) {
            uint4 u = pack_half8(hacc[i]);
            *reinterpret_cast<uint4*>(g_h1h + (size_t)n * Dd + tx * 8) = u;
        }
    }
}

// ---------------- z GEMM: y<3 -> z_r = (h1*d_out_r)@G_r ; y==3 -> out = x@Gx + c
__launch_bounds__(256)
__global__ void k_gemmz(float* __restrict__ out) {
    __shared__ __align__(16) __half Ah[64 * 136];
    __shared__ __align__(16) float  Cs[64 * 68];
    int tid = threadIdx.x;
    int warp = tid >> 5;
    int wr = warp >> 1, wc = warp & 1;
    int n0 = blockIdx.x << 6;
    int y = blockIdx.y;

    const __half* Asrc = (y < 3) ? g_h1h : g_xh;
#pragma unroll
    for (int it = 0; it < 8; ++it) {
        int idx = it * 256 + tid;            // 2048 uint2 total
        int row = idx >> 5, c4 = idx & 31;
        uint2 u = __ldg(reinterpret_cast<const uint2*>(Asrc + (size_t)(n0 + row) * Dd) + c4);
        if (y < 3) {
            int n = n0 + row;
            float s = (n < Nn) ? __ldg(g_dinv_out + y * Nn + n) : 0.f;
            float4 f = make_float4(0.f, 0.f, 0.f, 0.f);
            acc_h4(f, u);
            __half2 p0 = __floats2half2_rn(f.x * s, f.y * s);
            __half2 p1 = __floats2half2_rn(f.z * s, f.w * s);
            u.x = *reinterpret_cast<unsigned*>(&p0);
            u.y = *reinterpret_cast<unsigned*>(&p1);
        }
        *reinterpret_cast<uint2*>(Ah + row * 136 + c4 * 4) = u;
    }
    __syncthreads();

    const __half* Bb = (y < 3) ? (g_Gh + (size_t)y * Dd * OUTD) : g_Gxh;
    wmma::fragment<wmma::accumulator, 16, 16, 16, float> acc[2];
#pragma unroll
    for (int f = 0; f < 2; ++f) wmma::fill_fragment(acc[f], 0.f);
#pragma unroll
    for (int k = 0; k < 8; ++k) {
        wmma::fragment<wmma::matrix_a, 16, 16, 16, __half, wmma::row_major> af;
        wmma::load_matrix_sync(af, Ah + (wr * 16) * 136 + k * 16, 136);
#pragma unroll
        for (int f = 0; f < 2; ++f) {
            wmma::fragment<wmma::matrix_b, 16, 16, 16, __half, wmma::row_major> bf;
            wmma::load_matrix_sync(bf, Bb + (k * 16) * OUTD + wc * 32 + f * 16, OUTD);
            wmma::mma_sync(acc[f], af, bf, acc[f]);
        }
    }
#pragma unroll
    for (int f = 0; f < 2; ++f)
        wmma::store_matrix_sync(Cs + (wr * 16) * 68 + wc * 32 + f * 16, acc[f], 68,
                                wmma::mem_row_major);
    __syncthreads();

    if (y < 3) {
#pragma unroll
        for (int it = 0; it < 8; ++it) {
            int idx = it * 256 + tid;        // 2048
            int row = idx >> 5, cp = idx & 31;
            int n = n0 + row;
            if (n < Nn) {
                __half2 p = __floats2half2_rn(Cs[row * 68 + cp * 2], Cs[row * 68 + cp * 2 + 1]);
                *(reinterpret_cast<unsigned*>(g_z + ((size_t)y * Nn + n) * OUTD) + cp) =
                    *reinterpret_cast<unsigned*>(&p);
            }
        }
    } else {
        // out = x@Gx + c  (base for the relation reds)
#pragma unroll
        for (int it = 0; it < 8; ++it) {
            int idx = it * 256 + tid;
            int row = idx >> 5, cp = idx & 31;
            int n = n0 + row;
            if (n < Nn) {
                float2 p;
                p.x = Cs[row * 68 + cp * 2]     + g_c[cp * 2];
                p.y = Cs[row * 68 + cp * 2 + 1] + g_c[cp * 2 + 1];
                *(reinterpret_cast<float2*>(out + (size_t)n * OUTD) + cp) = p;
            }
        }
    }
}

// ---------------- combine: one warp per (r,n); red.v2 into out -----------------
__launch_bounds__(256)
__global__ void k_combine(float* __restrict__ out) {
    int gw = (blockIdx.x * blockDim.x + threadIdx.x) >> 5;   // (r,n)
    if (gw >= Rr * Nn) return;
    int lane = threadIdx.x & 31;
    int n = gw % Nn;
    const __half* zb = g_z + (size_t)(gw / Nn) * Nn * OUTD;

    int beg = __ldg(g_rowstart + gw);
    int end = beg + __ldg(g_deg_in + gw);
    float2 acc = make_float2(0.f, 0.f);
    int e = beg;
#pragma unroll 1
    for (; e + 4 <= end; e += 4) {
        int s0 = __ldg(g_col + e);
        int s1 = __ldg(g_col + e + 1);
        int s2 = __ldg(g_col + e + 2);
        int s3 = __ldg(g_col + e + 3);
        unsigned u0 = __ldg(reinterpret_cast<const unsigned*>(zb + (size_t)s0 * OUTD) + lane);
        unsigned u1 = __ldg(reinterpret_cast<const unsigned*>(zb + (size_t)s1 * OUTD) + lane);
        unsigned u2 = __ldg(reinterpret_cast<const unsigned*>(zb + (size_t)s2 * OUTD) + lane);
        unsigned u3 = __ldg(reinterpret_cast<const unsigned*>(zb + (size_t)s3 * OUTD) + lane);
        float2 f0 = __half22float2(*reinterpret_cast<__half2*>(&u0));
        float2 f1 = __half22float2(*reinterpret_cast<__half2*>(&u1));
        float2 f2 = __half22float2(*reinterpret_cast<__half2*>(&u2));
        float2 f3 = __half22float2(*reinterpret_cast<__half2*>(&u3));
        acc.x += f0.x + f1.x + f2.x + f3.x;
        acc.y += f0.y + f1.y + f2.y + f3.y;
    }
#pragma unroll 1
    for (; e < end; ++e) {
        int s0 = __ldg(g_col + e);
        unsigned u0 = __ldg(reinterpret_cast<const unsigned*>(zb + (size_t)s0 * OUTD) + lane);
        float2 f0 = __half22float2(*reinterpret_cast<__half2*>(&u0));
        acc.x += f0.x; acc.y += f0.y;
    }
    float di = __ldg(g_dinv_in + gw);
    float vx = acc.x * di, vy = acc.y * di;
    float* p = out + (size_t)n * OUTD + lane * 2;
    asm volatile("red.global.add.v2.f32 [%0], {%1,%2};"
                 :: "l"(p), "f"(vx), "f"(vy) : "memory");
}

// ---------------- launch ------------------------------------------------------
extern "C" void kernel_launch(void* const* d_in, const int* in_sizes, int n_in,
                              void* d_out, int out_size) {
    const float* x    = (const float*)d_in[0];
    const int*   src  = (const int*)  d_in[1];
    const int*   dst  = (const int*)  d_in[2];
    const float* W1   = (const float*)d_in[3];
    const float* b1   = (const float*)d_in[4];
    const float* W2   = (const float*)d_in[5];
    const float* b2   = (const float*)d_in[6];
    const float* Wlin = (const float*)d_in[7];
    const float* blin = (const float*)d_in[8];
    float* out = (float*)d_out;

    k_init<<<(Rr * Nn + 255) / 256, 256>>>();
    k_degree_prep<<<DEG_BLOCKS + P1_BLOCKS + PW1_BLOCKS, 256>>>(src, dst, W2, Wlin, W1);
    k_rowstart_prep<<<RS_BLOCKS + P2_BLOCKS, 256>>>(b2, Wlin, blin);
    k_csrfill_prescale<<<CF_BLOCKS + PS_BLOCKS, 256>>>(src, dst, x);

    const int gather_blocks = (Rr * Nn * 32 + 255) / 256;   // one warp per (r,n)
    // layer 1
    k_gather1<<<gather_blocks, 256>>>();
    k_gemm1<<<(Nn + 63) / 64, 256>>>(b1);
    // layer 2: project to 64-dim, init out, gather+red
    dim3 zgrid((Nn + 63) / 64, 4);
    k_gemmz<<<zgrid, 256>>>(out);
    k_combine<<<gather_blocks, 256>>>(out);
}